// round 3
// baseline (speedup 1.0000x reference)
#include <cuda_runtime.h>

#define SQ 256      // sequence length
#define DH 32       // head dim
#define KPAD 36     // padded K row stride (floats) for conflict-free LDS.128

// smem layout (floats):
//   Ks: 256*36  = 9216
//   Vs: 256*32  = 8192
//   Ms: 256
//   Ps: 8*256   = 2048
// total 19712 floats = 78848 bytes
#define SMEM_FLOATS (SQ*KPAD + SQ*DH + SQ + 8*SQ)

__global__ __launch_bounds__(256, 2)
void TFA_88089779241014_kernel(const float* __restrict__ q,
                               const float* __restrict__ k,
                               const float* __restrict__ v,
                               const float* __restrict__ mask,
                               const float* __restrict__ tri,
                               float* __restrict__ out) {
    extern __shared__ float sm[];
    float* Ks = sm;                  // [256][36]
    float* Vs = Ks + SQ * KPAD;      // [256][32]
    float* Ms = Vs + SQ * DH;        // [256]
    float* Ps = Ms + SQ;             // [8][256] (one row per warp)

    const int bx   = blockIdx.x;     // n*4 + h
    const int n    = bx >> 2;
    const int h    = bx & 3;
    const int tid  = threadIdx.x;
    const int lane = tid & 31;
    const int wid  = tid >> 5;

    const float* qb = q   + (size_t)bx * SQ * DH;
    const float* kb = k   + (size_t)bx * SQ * DH;
    const float* vb = v   + (size_t)bx * SQ * DH;
    float*       ob = out + (size_t)bx * SQ * DH;
    const float* mb = mask + (size_t)n * SQ;
    const float* tb = tri  + (size_t)h * SQ * SQ;

    // ---- stage K (padded) and V (linear) into smem, coalesced float4 ----
    for (int i = tid; i < SQ * DH / 4; i += 256) {
        float4 kk = ((const float4*)kb)[i];
        int row = i >> 3;            // 8 float4 per row
        int col = (i & 7) << 2;
        *(float4*)&Ks[row * KPAD + col] = kk;
        ((float4*)Vs)[i] = ((const float4*)vb)[i];
    }
    Ms[tid] = mb[tid];
    __syncthreads();

    const float scale = 0.17677669529663687f;   // 1/sqrt(32)
    float* Pw = Ps + wid * SQ;                  // warp-private P row

    for (int qt = 0; qt < SQ / 8; qt++) {
        const int s = qt * 8 + wid;             // this warp's query row

        // q row into registers (uniform-address LDG, broadcast)
        float4 qv[8];
        const float4* qr = (const float4*)(qb + s * DH);
        #pragma unroll
        for (int i = 0; i < 8; i++) qv[i] = qr[i];

        // prefetch triangle bias for this lane's 8 keys (coalesced, L2-resident)
        float trir[8];
        const float* tr = tb + (size_t)s * SQ;
        #pragma unroll
        for (int j = 0; j < 8; j++) trir[j] = tr[j * 32 + lane];

        // ---- QK^T: lane handles keys t = 32j + lane ----
        float sc[8];
        #pragma unroll
        for (int j = 0; j < 8; j++) {
            const int t = j * 32 + lane;
            const float* kr = &Ks[t * KPAD];
            float acc = 0.f;
            #pragma unroll
            for (int d4 = 0; d4 < 8; d4++) {
                float4 kk = *(const float4*)&kr[d4 * 4];
                acc += qv[d4].x * kk.x;
                acc += qv[d4].y * kk.y;
                acc += qv[d4].z * kk.z;
                acc += qv[d4].w * kk.w;
            }
            sc[j] = acc * scale + Ms[t] + trir[j];
        }

        // ---- softmax (warp reduction) ----
        float m = sc[0];
        #pragma unroll
        for (int j = 1; j < 8; j++) m = fmaxf(m, sc[j]);
        #pragma unroll
        for (int o = 16; o > 0; o >>= 1)
            m = fmaxf(m, __shfl_xor_sync(0xffffffffu, m, o));

        float sum = 0.f;
        #pragma unroll
        for (int j = 0; j < 8; j++) { sc[j] = __expf(sc[j] - m); sum += sc[j]; }
        #pragma unroll
        for (int o = 16; o > 0; o >>= 1)
            sum += __shfl_xor_sync(0xffffffffu, sum, o);
        const float rinv = 1.f / sum;

        #pragma unroll
        for (int j = 0; j < 8; j++) Pw[j * 32 + lane] = sc[j] * rinv;
        __syncwarp();

        // ---- PV: lane = output dim d; P broadcast LDS.128, V conflict-free ----
        float acc = 0.f;
        #pragma unroll 8
        for (int t4 = 0; t4 < SQ / 4; t4++) {
            float4 pp = *(const float4*)&Pw[t4 * 4];
            acc += pp.x * Vs[(t4 * 4 + 0) * DH + lane];
            acc += pp.y * Vs[(t4 * 4 + 1) * DH + lane];
            acc += pp.z * Vs[(t4 * 4 + 2) * DH + lane];
            acc += pp.w * Vs[(t4 * 4 + 3) * DH + lane];
        }
        ob[s * DH + lane] = acc;
        __syncwarp();   // protect Pw before next tile overwrites it
    }
}

extern "C" void kernel_launch(void* const* d_in, const int* in_sizes, int n_in,
                              void* d_out, int out_size) {
    const float* q    = (const float*)d_in[0];
    const float* k    = (const float*)d_in[1];
    const float* v    = (const float*)d_in[2];
    const float* mask = (const float*)d_in[3];
    const float* tri  = (const float*)d_in[4];
    float* out = (float*)d_out;

    const int smem_bytes = SMEM_FLOATS * sizeof(float);   // 78848
    cudaFuncSetAttribute(TFA_88089779241014_kernel,
                         cudaFuncAttributeMaxDynamicSharedMemorySize, smem_bytes);

    // one CTA per (n, h) head: 256*4 = 1024 CTAs
    TFA_88089779241014_kernel<<<1024, 256, smem_bytes>>>(q, k, v, mask, tri, out);
}

// round 5
// speedup vs baseline: 5.0101x; 5.0101x over previous
#include <cuda_runtime.h>
#include <cuda_bf16.h>
#include <cstdint>

#define LOG2E 1.4426950408889634f
#define C1 (0.17677669529663687f * LOG2E)   // sm_scale * log2(e)

// smem layout (bytes)
#define OFF_MS 0                      // mask * log2e, 256 f32 (1024 B)
#define OFF_KH 1024                   // K hi bf16 [256][32], row stride 80 B
#define OFF_KL (OFF_KH + 256*80)      // K lo
#define OFF_VH (OFF_KL + 256*80)      // Vt hi bf16 [32][256], row stride 528 B
#define OFF_VL (OFF_VH + 32*528)      // Vt lo
#define SMEM_TOTAL (OFF_VL + 32*528)  // 75776 B

__device__ __forceinline__ float ex2f(float x) {
    float y; asm("ex2.approx.ftz.f32 %0, %1;" : "=f"(y) : "f"(x)); return y;
}
__device__ __forceinline__ uint32_t pack2(float a, float b) {
    __nv_bfloat162 t = __floats2bfloat162_rn(a, b);   // low half = a
    return *(uint32_t*)&t;
}
__device__ __forceinline__ void split2(float2 x, uint32_t& hi, uint32_t& lo) {
    __nv_bfloat162 hv = __floats2bfloat162_rn(x.x, x.y);
    float2 hf = __bfloat1622float2(hv);
    hi = *(uint32_t*)&hv;
    lo = pack2(x.x - hf.x, x.y - hf.y);
}
__device__ __forceinline__ void mma16816(float* d, const uint32_t* a,
                                         uint32_t b0, uint32_t b1) {
    asm volatile(
        "mma.sync.aligned.m16n8k16.row.col.f32.bf16.bf16.f32 "
        "{%0,%1,%2,%3}, {%4,%5,%6,%7}, {%8,%9}, {%0,%1,%2,%3};"
        : "+f"(d[0]), "+f"(d[1]), "+f"(d[2]), "+f"(d[3])
        : "r"(a[0]), "r"(a[1]), "r"(a[2]), "r"(a[3]), "r"(b0), "r"(b1));
}

__global__ __launch_bounds__(256, 2)
void TFA_88089779241014_kernel(const float* __restrict__ q,
                               const float* __restrict__ k,
                               const float* __restrict__ v,
                               const float* __restrict__ mask,
                               const float* __restrict__ tri,
                               float* __restrict__ out) {
    extern __shared__ char smem[];

    const int tid  = threadIdx.x;
    const int lane = tid & 31;
    const int wid  = tid >> 5;
    const int g    = lane >> 2;         // group id (row within fragment)
    const int tg   = lane & 3;          // thread in group
    const int c    = tg * 2;            // column pair base

    const int bx   = blockIdx.x;        // head*2 + mtile
    const int head = bx >> 1;           // n*4 + h
    const int mt   = bx & 1;
    const int n    = head >> 2;
    const int h    = head & 3;

    const float* kb = k + (size_t)head * 8192;
    const float* vb = v + (size_t)head * 8192;
    const float* mb = mask + (size_t)n * 256;

    // ---- stage K as bf16 hi/lo, [t][d] rows, 80B stride (conflict-free B frags) ----
    for (int i = tid; i < 4096; i += 256) {
        int t = i >> 4, c2 = (i & 15) << 1;
        float2 x = *(const float2*)(kb + t * 32 + c2);
        uint32_t hi, lo; split2(x, hi, lo);
        *(uint32_t*)(smem + OFF_KH + t * 80 + c2 * 2) = hi;
        *(uint32_t*)(smem + OFF_KL + t * 80 + c2 * 2) = lo;
    }
    // ---- stage V transposed: Vt[d][t] bf16 hi/lo, 528B stride ----
    for (int i = tid; i < 2048; i += 256) {
        float4 x = ((const float4*)vb)[i];
        int t = i >> 3, d4 = (i & 7) << 2;
        float e[4] = {x.x, x.y, x.z, x.w};
        #pragma unroll
        for (int j = 0; j < 4; j++) {
            int d = d4 + j;
            __nv_bfloat16 hv = __float2bfloat16_rn(e[j]);
            __nv_bfloat16 lv = __float2bfloat16_rn(e[j] - __bfloat162float(hv));
            *(__nv_bfloat16*)(smem + OFF_VH + d * 528 + t * 2) = hv;
            *(__nv_bfloat16*)(smem + OFF_VL + d * 528 + t * 2) = lv;
        }
    }
    for (int i = tid; i < 256; i += 256)
        *(float*)(smem + OFF_MS + i * 4) = mb[i] * LOG2E;

    // ---- Q fragments for this warp's 16 rows (held in registers all kernel) ----
    const int rowbase = mt * 128 + wid * 16;
    const float* qrow = q + (size_t)head * 8192 + (size_t)rowbase * 32;
    uint32_t qhi[2][4], qlo[2][4];
    #pragma unroll
    for (int s = 0; s < 2; s++) {
        int k0 = s * 16;
        split2(*(const float2*)(qrow + (g)     * 32 + k0 + c),     qhi[s][0], qlo[s][0]);
        split2(*(const float2*)(qrow + (g + 8) * 32 + k0 + c),     qhi[s][1], qlo[s][1]);
        split2(*(const float2*)(qrow + (g)     * 32 + k0 + 8 + c), qhi[s][2], qlo[s][2]);
        split2(*(const float2*)(qrow + (g + 8) * 32 + k0 + 8 + c), qhi[s][3], qlo[s][3]);
    }

    const float* trow  = tri + (size_t)h * 65536 + (size_t)(rowbase + g) * 256;
    const float* trow8 = trow + 8 * 256;

    __syncthreads();

    float acc[4][4];
    #pragma unroll
    for (int dn = 0; dn < 4; dn++)
        #pragma unroll
        for (int j = 0; j < 4; j++) acc[dn][j] = 0.f;
    float sum_g = 0.f, sum_h = 0.f;

    // ================= main loop over 16-key tiles =================
    #pragma unroll 1
    for (int kt = 0; kt < 16; kt++) {
        const int n0 = kt * 16;

        // triangle bias (L2-resident) for this tile
        float2 tA = *(const float2*)(trow  + n0 + c);
        float2 tB = *(const float2*)(trow  + n0 + 8 + c);
        float2 tC = *(const float2*)(trow8 + n0 + c);
        float2 tD = *(const float2*)(trow8 + n0 + 8 + c);

        // ---- QK^T: two n8 tiles, K=32 (2 ksteps), 3 split products ----
        float d0[4] = {0.f, 0.f, 0.f, 0.f};
        float d1[4] = {0.f, 0.f, 0.f, 0.f};
        #pragma unroll
        for (int s = 0; s < 2; s++) {
            const char* kA = smem + (n0 + g)     * 80 + s * 32 + tg * 4;
            const char* kB = smem + (n0 + 8 + g) * 80 + s * 32 + tg * 4;
            uint32_t bAh0 = *(const uint32_t*)(kA + OFF_KH);
            uint32_t bAh1 = *(const uint32_t*)(kA + OFF_KH + 16);
            uint32_t bAl0 = *(const uint32_t*)(kA + OFF_KL);
            uint32_t bAl1 = *(const uint32_t*)(kA + OFF_KL + 16);
            uint32_t bBh0 = *(const uint32_t*)(kB + OFF_KH);
            uint32_t bBh1 = *(const uint32_t*)(kB + OFF_KH + 16);
            uint32_t bBl0 = *(const uint32_t*)(kB + OFF_KL);
            uint32_t bBl1 = *(const uint32_t*)(kB + OFF_KL + 16);
            mma16816(d0, qhi[s], bAh0, bAh1);
            mma16816(d0, qhi[s], bAl0, bAl1);
            mma16816(d0, qlo[s], bAh0, bAh1);
            mma16816(d1, qhi[s], bBh0, bBh1);
            mma16816(d1, qhi[s], bBl0, bBl1);
            mma16816(d1, qlo[s], bBh0, bBh1);
        }

        // ---- bias + exp2 (no max subtraction; fp32-safe) ----
        float2 msA = *(const float2*)(smem + OFF_MS + (n0 + c) * 4);
        float2 msB = *(const float2*)(smem + OFF_MS + (n0 + 8 + c) * 4);
        float e00 = ex2f(fmaf(d0[0], C1, fmaf(tA.x, LOG2E, msA.x)));
        float e01 = ex2f(fmaf(d0[1], C1, fmaf(tA.y, LOG2E, msA.y)));
        float e02 = ex2f(fmaf(d0[2], C1, fmaf(tC.x, LOG2E, msA.x)));
        float e03 = ex2f(fmaf(d0[3], C1, fmaf(tC.y, LOG2E, msA.y)));
        float e10 = ex2f(fmaf(d1[0], C1, fmaf(tB.x, LOG2E, msB.x)));
        float e11 = ex2f(fmaf(d1[1], C1, fmaf(tB.y, LOG2E, msB.y)));
        float e12 = ex2f(fmaf(d1[2], C1, fmaf(tD.x, LOG2E, msB.x)));
        float e13 = ex2f(fmaf(d1[3], C1, fmaf(tD.y, LOG2E, msB.y)));
        sum_g += (e00 + e01) + (e10 + e11);
        sum_h += (e02 + e03) + (e12 + e13);

        // ---- P fragments (D-frag layout == A-frag layout; just convert) ----
        uint32_t ph[4], pl[4];
        {
            float2 x;
            x.x = e00; x.y = e01; split2(x, ph[0], pl[0]);
            x.x = e02; x.y = e03; split2(x, ph[1], pl[1]);
            x.x = e10; x.y = e11; split2(x, ph[2], pl[2]);
            x.x = e12; x.y = e13; split2(x, ph[3], pl[3]);
        }

        // ---- PV: out[16 x 32] += P[16 x 16] * V[16keys x 32] ----
        #pragma unroll
        for (int dn = 0; dn < 4; dn++) {
            const char* vrow = smem + (dn * 8 + g) * 528 + n0 * 2 + tg * 4;
            uint32_t vh0 = *(const uint32_t*)(vrow + OFF_VH);
            uint32_t vh1 = *(const uint32_t*)(vrow + OFF_VH + 16);
            uint32_t vl0 = *(const uint32_t*)(vrow + OFF_VL);
            uint32_t vl1 = *(const uint32_t*)(vrow + OFF_VL + 16);
            mma16816(acc[dn], ph, vh0, vh1);
            mma16816(acc[dn], ph, vl0, vl1);
            mma16816(acc[dn], pl, vh0, vh1);
        }
    }

    // ---- row-sum reduce within quad (lanes sharing row g) ----
    sum_g += __shfl_xor_sync(0xffffffffu, sum_g, 1);
    sum_g += __shfl_xor_sync(0xffffffffu, sum_g, 2);
    sum_h += __shfl_xor_sync(0xffffffffu, sum_h, 1);
    sum_h += __shfl_xor_sync(0xffffffffu, sum_h, 2);
    const float rg = 1.f / sum_g;
    const float rh = 1.f / sum_h;

    // ---- store ----
    float* orow = out + (size_t)head * 8192 + (size_t)rowbase * 32;
    #pragma unroll
    for (int dn = 0; dn < 4; dn++) {
        float2 w0 = {acc[dn][0] * rg, acc[dn][1] * rg};
        float2 w1 = {acc[dn][2] * rh, acc[dn][3] * rh};
        *(float2*)(orow + (g)     * 32 + dn * 8 + c) = w0;
        *(float2*)(orow + (g + 8) * 32 + dn * 8 + c) = w1;
    }
}

extern "C" void kernel_launch(void* const* d_in, const int* in_sizes, int n_in,
                              void* d_out, int out_size) {
    const float* q    = (const float*)d_in[0];
    const float* k    = (const float*)d_in[1];
    const float* v    = (const float*)d_in[2];
    const float* mask = (const float*)d_in[3];
    const float* tri  = (const float*)d_in[4];
    float* out = (float*)d_out;

    cudaFuncSetAttribute(TFA_88089779241014_kernel,
                         cudaFuncAttributeMaxDynamicSharedMemorySize, SMEM_TOTAL);
    // 1024 heads x 2 query tiles of 128
    TFA_88089779241014_kernel<<<2048, 256, SMEM_TOTAL>>>(q, k, v, mask, tri, out);
}